// round 1
// baseline (speedup 1.0000x reference)
#include <cuda_runtime.h>
#include <math.h>

// ---------------------------------------------------------------------------
// AttentionLayer: out = (wn_out(ctx) + x)*√½ ;  ctx = softmax(h @ (enc0+enc1)) @ enc2 * √S
//                 h = (wn_in(x) + te)*√½
// B=64, T=1024, S=1024, C=E=512.  Output = concat(out [B,T,C], attn [B,T,S]).
// ---------------------------------------------------------------------------

#define BM 128
#define BN 128
#define BK 8

static const float SQRT_HALF_F = 0.70710678118654752440f;

// scratch (device-global: no runtime allocation allowed)
__device__ float g_h[(size_t)64 * 1024 * 512];     // 128 MiB
__device__ float g_ctx[(size_t)64 * 1024 * 512];   // 128 MiB
__device__ float g_win[512 * 512];
__device__ float g_wout[512 * 512];

// ---------------------------------------------------------------------------
// weight-norm: w[r,:] = v[r,:] * g[r] / ||v[r,:]||   (one block per row)
// ---------------------------------------------------------------------------
__global__ void wn_kernel(const float* __restrict__ v, const float* __restrict__ g,
                          float* __restrict__ w, int cols)
{
    int r = blockIdx.x;
    int tid = threadIdx.x;
    const float* vr = v + (size_t)r * cols;

    float ss = 0.f;
    for (int c = tid; c < cols; c += blockDim.x) {
        float t = vr[c];
        ss += t * t;
    }
    __shared__ float sm[32];
    #pragma unroll
    for (int o = 16; o > 0; o >>= 1) ss += __shfl_down_sync(0xffffffffu, ss, o);
    int warp = tid >> 5, lane = tid & 31;
    if (lane == 0) sm[warp] = ss;
    __syncthreads();
    int nw = blockDim.x >> 5;
    if (warp == 0) {
        float s2 = (lane < nw) ? sm[lane] : 0.f;
        #pragma unroll
        for (int o = 16; o > 0; o >>= 1) s2 += __shfl_down_sync(0xffffffffu, s2, o);
        if (lane == 0) sm[0] = s2;
    }
    __syncthreads();
    float scale = g[r] / sqrtf(sm[0]);
    float* wr = w + (size_t)r * cols;
    for (int c = tid; c < cols; c += blockDim.x) wr[c] = vr[c] * scale;
}

// ---------------------------------------------------------------------------
// Tiled fp32 GEMM, 128x128x8, 256 threads, 8x8 accum per thread.
//   BTRANS: B is [N,K] row-major (NT gemm) ; else B is [K,N] row-major (NN).
//   SUMB:   B operand = B0 + B1 (elementwise, same layout).
//   EPI==0: C = acc * scale
//   EPI==1: C = (acc + bias[col] + addend[row*N+col]) * scale   (z must be 0)
// Requirements: M%128==0, N%128==0, K%8==0, K%4==0 alignment (all satisfied).
// ---------------------------------------------------------------------------
template <bool BTRANS, bool SUMB, int EPI>
__global__ __launch_bounds__(256, 2)
void gemm_kernel(const float* __restrict__ A, const float* __restrict__ B0,
                 const float* __restrict__ B1, float* __restrict__ C,
                 int M, int N, int K,
                 long long sA, long long sB, long long sC,
                 const float* __restrict__ bias,
                 const float* __restrict__ addend,
                 float scale)
{
    int z = blockIdx.z;
    A += (size_t)z * sA;
    B0 += (size_t)z * sB;
    if (SUMB) B1 += (size_t)z * sB;
    C += (size_t)z * sC;

    __shared__ float As[BK][BM];
    __shared__ float Bs[BK][BN];

    int tid = threadIdx.x;
    int tx = tid & 15;        // col group 0..15
    int ty = tid >> 4;        // row group 0..15
    int m0 = blockIdx.y * BM;
    int n0 = blockIdx.x * BN;

    float acc[8][8];
    #pragma unroll
    for (int i = 0; i < 8; i++)
        #pragma unroll
        for (int j = 0; j < 8; j++) acc[i][j] = 0.f;

    // loader indices
    int arow = tid >> 1;           // 0..127
    int akk  = (tid & 1) * 4;      // 0 or 4
    int bkr  = tid >> 5;           // 0..7   (NN path)
    int bn4  = (tid & 31) * 4;     // 0..124 (NN path)

    for (int k0 = 0; k0 < K; k0 += BK) {
        // ---- load A tile (transpose into As[k][m]) ----
        float4 av = *(const float4*)&A[(size_t)(m0 + arow) * K + k0 + akk];
        As[akk + 0][arow] = av.x;
        As[akk + 1][arow] = av.y;
        As[akk + 2][arow] = av.z;
        As[akk + 3][arow] = av.w;

        // ---- load B tile ----
        if (BTRANS) {
            float4 bv = *(const float4*)&B0[(size_t)(n0 + arow) * K + k0 + akk];
            Bs[akk + 0][arow] = bv.x;
            Bs[akk + 1][arow] = bv.y;
            Bs[akk + 2][arow] = bv.z;
            Bs[akk + 3][arow] = bv.w;
        } else {
            size_t boff = (size_t)(k0 + bkr) * N + n0 + bn4;
            float4 bv = *(const float4*)&B0[boff];
            if (SUMB) {
                float4 b1 = *(const float4*)&B1[boff];
                bv.x += b1.x; bv.y += b1.y; bv.z += b1.z; bv.w += b1.w;
            }
            *(float4*)&Bs[bkr][bn4] = bv;
        }
        __syncthreads();

        #pragma unroll
        for (int k = 0; k < BK; k++) {
            float a[8], b[8];
            #pragma unroll
            for (int i = 0; i < 8; i++) a[i] = As[k][ty + 16 * i];
            #pragma unroll
            for (int j = 0; j < 8; j++) b[j] = Bs[k][tx + 16 * j];
            #pragma unroll
            for (int i = 0; i < 8; i++)
                #pragma unroll
                for (int j = 0; j < 8; j++)
                    acc[i][j] = fmaf(a[i], b[j], acc[i][j]);
        }
        __syncthreads();
    }

    #pragma unroll
    for (int i = 0; i < 8; i++) {
        int row = m0 + ty + 16 * i;
        #pragma unroll
        for (int j = 0; j < 8; j++) {
            int col = n0 + tx + 16 * j;
            float r = acc[i][j];
            if (EPI == 1) {
                r = (r + bias[col] + addend[(size_t)row * N + col]) * scale;
            } else {
                r = r * scale;
            }
            C[(size_t)row * N + col] = r;
        }
    }
}

// ---------------------------------------------------------------------------
// row softmax over S=1024, in place. One block (256 thr) per row; 4 elems/thr.
// ---------------------------------------------------------------------------
__global__ void softmax_kernel(float* __restrict__ attn)
{
    size_t row = blockIdx.x;
    float* p = attn + row * 1024;
    int tid = threadIdx.x;

    float4 v = *(const float4*)&p[tid * 4];

    __shared__ float sm[8];

    // row max
    float m = fmaxf(fmaxf(v.x, v.y), fmaxf(v.z, v.w));
    #pragma unroll
    for (int o = 16; o > 0; o >>= 1) m = fmaxf(m, __shfl_xor_sync(0xffffffffu, m, o));
    if ((tid & 31) == 0) sm[tid >> 5] = m;
    __syncthreads();
    float rmax = sm[0];
    #pragma unroll
    for (int w = 1; w < 8; w++) rmax = fmaxf(rmax, sm[w]);

    float e0 = expf(v.x - rmax);
    float e1 = expf(v.y - rmax);
    float e2 = expf(v.z - rmax);
    float e3 = expf(v.w - rmax);

    float s = (e0 + e1) + (e2 + e3);
    #pragma unroll
    for (int o = 16; o > 0; o >>= 1) s += __shfl_xor_sync(0xffffffffu, s, o);
    __syncthreads();                     // everyone done reading sm (max)
    if ((tid & 31) == 0) sm[tid >> 5] = s;
    __syncthreads();
    float rsum = 0.f;
    #pragma unroll
    for (int w = 0; w < 8; w++) rsum += sm[w];
    float inv = 1.f / rsum;

    float4 o4 = make_float4(e0 * inv, e1 * inv, e2 * inv, e3 * inv);
    *(float4*)&p[tid * 4] = o4;
}

// ---------------------------------------------------------------------------
extern "C" void kernel_launch(void* const* d_in, const int* in_sizes, int n_in,
                              void* d_out, int out_size)
{
    const float* x     = (const float*)d_in[0];   // [64,1024,512]
    const float* te    = (const float*)d_in[1];   // [64,1024,512]
    const float* enc0  = (const float*)d_in[2];   // [64,512,1024]
    const float* enc1  = (const float*)d_in[3];   // [64,512,1024]
    const float* enc2  = (const float*)d_in[4];   // [64,1024,512]
    const float* in_v  = (const float*)d_in[5];   // [512,512]
    const float* in_g  = (const float*)d_in[6];   // [512]
    const float* in_b  = (const float*)d_in[7];   // [512]
    const float* out_v = (const float*)d_in[8];   // [512,512]
    const float* out_g = (const float*)d_in[9];   // [512]
    const float* out_b = (const float*)d_in[10];  // [512]

    float* out  = (float*)d_out;                          // [64*1024*512]
    float* attn = out + (size_t)64 * 1024 * 512;          // [64*1024*1024]

    float *h, *ctx, *win, *wout;
    cudaGetSymbolAddress((void**)&h,    g_h);
    cudaGetSymbolAddress((void**)&ctx,  g_ctx);
    cudaGetSymbolAddress((void**)&win,  g_win);
    cudaGetSymbolAddress((void**)&wout, g_wout);

    dim3 blk(256);

    // normalized weights
    wn_kernel<<<512, 256>>>(in_v,  in_g,  win,  512);
    wn_kernel<<<512, 256>>>(out_v, out_g, wout, 512);

    // K1: h = (x @ W_in^T + in_b + te) * sqrt(0.5)      M=65536 N=512 K=512 (NT)
    gemm_kernel<true, false, 1><<<dim3(512 / BN, 65536 / BM, 1), blk>>>(
        x, win, nullptr, h, 65536, 512, 512,
        0LL, 0LL, 0LL, in_b, te, SQRT_HALF_F);

    // K2: scores = h @ (enc0+enc1)  per batch: M=1024 N=1024 K=512 (NN, summed B)
    gemm_kernel<false, true, 0><<<dim3(1024 / BN, 1024 / BM, 64), blk>>>(
        h, enc0, enc1, attn, 1024, 1024, 512,
        (long long)1024 * 512, (long long)512 * 1024, (long long)1024 * 1024,
        nullptr, nullptr, 1.0f);

    // K3: softmax over S, in place in the attn output region
    softmax_kernel<<<65536, 256>>>(attn);

    // K4: ctx = (attn @ enc2) * sqrt(S)=32  per batch: M=1024 N=512 K=1024 (NN)
    gemm_kernel<false, false, 0><<<dim3(512 / BN, 1024 / BM, 64), blk>>>(
        attn, enc2, nullptr, ctx, 1024, 512, 1024,
        (long long)1024 * 1024, (long long)1024 * 512, (long long)1024 * 512,
        nullptr, nullptr, 32.0f);

    // K5: out = (ctx @ W_out^T + out_b + x) * sqrt(0.5)  M=65536 N=512 K=512 (NT)
    gemm_kernel<true, false, 1><<<dim3(512 / BN, 65536 / BM, 1), blk>>>(
        ctx, wout, nullptr, out, 65536, 512, 512,
        0LL, 0LL, 0LL, out_b, x, SQRT_HALF_F);
}

// round 2
// speedup vs baseline: 1.1077x; 1.1077x over previous
#include <cuda_runtime.h>
#include <math.h>

// ---------------------------------------------------------------------------
// AttentionLayer fused pipeline, fp32 with packed FFMA2 (f32x2) GEMMs.
// B=64, T=1024, S=1024, C=E=512.  Output = concat(out [B,T,C], attn [B,T,S]).
// ---------------------------------------------------------------------------

#define BM 128
#define BN 128
#define BK 16
#define LDST 132   // smem row stride (BM + 4 pad)

static const float SQRT_HALF_F = 0.70710678118654752440f;

// scratch (device globals: runtime allocation forbidden)
__device__ float g_h[(size_t)64 * 1024 * 512];      // 128 MiB
__device__ float g_ctx[(size_t)64 * 1024 * 512];    // 128 MiB
__device__ float g_esum[(size_t)64 * 512 * 1024];   // 128 MiB (enc0+enc1)
__device__ float g_win[512 * 512];
__device__ float g_wout[512 * 512];

// ---------------------------------------------------------------------------
// weight-norm: w[r,:] = v[r,:] * g[r] / ||v[r,:]||   (one block per row)
// ---------------------------------------------------------------------------
__global__ void wn_kernel(const float* __restrict__ v, const float* __restrict__ g,
                          float* __restrict__ w, int cols)
{
    int r = blockIdx.x;
    int tid = threadIdx.x;
    const float* vr = v + (size_t)r * cols;

    float ss = 0.f;
    for (int c = tid; c < cols; c += blockDim.x) {
        float t = vr[c];
        ss += t * t;
    }
    __shared__ float sm[32];
    #pragma unroll
    for (int o = 16; o > 0; o >>= 1) ss += __shfl_down_sync(0xffffffffu, ss, o);
    int warp = tid >> 5, lane = tid & 31;
    if (lane == 0) sm[warp] = ss;
    __syncthreads();
    int nw = blockDim.x >> 5;
    if (warp == 0) {
        float s2 = (lane < nw) ? sm[lane] : 0.f;
        #pragma unroll
        for (int o = 16; o > 0; o >>= 1) s2 += __shfl_down_sync(0xffffffffu, s2, o);
        if (lane == 0) sm[0] = s2;
    }
    __syncthreads();
    float scale = g[r] / sqrtf(sm[0]);
    float* wr = w + (size_t)r * cols;
    for (int c = tid; c < cols; c += blockDim.x) wr[c] = vr[c] * scale;
}

// ---------------------------------------------------------------------------
// elementwise sum: esum = enc0 + enc1  (float4 per thread)
// ---------------------------------------------------------------------------
__global__ void esum_kernel(const float4* __restrict__ a, const float4* __restrict__ b,
                            float4* __restrict__ o)
{
    size_t i = (size_t)blockIdx.x * blockDim.x + threadIdx.x;
    float4 va = a[i], vb = b[i];
    o[i] = make_float4(va.x + vb.x, va.y + vb.y, va.z + vb.z, va.w + vb.w);
}

// ---------------------------------------------------------------------------
// fp32 GEMM with packed f32x2 FMA. 128x128x16 tiles, 256 threads, 8x8/thread.
//   BTRANS: B is [N,K] row-major (NT) ; else B is [K,N] row-major (NN).
//   EPI==0: C = acc * scale
//   EPI==1: C = (acc + bias[col] + addend[row*N+col]) * scale (z must be 0)
// Requires M%128==0, N%128==0, K%16==0 (all satisfied here).
// ---------------------------------------------------------------------------
template <bool BTRANS, int EPI>
__global__ __launch_bounds__(256, 2)
void gemm2_kernel(const float* __restrict__ A, const float* __restrict__ B,
                  float* __restrict__ C, int M, int N, int K,
                  long long sA, long long sB, long long sC,
                  const float* __restrict__ bias,
                  const float* __restrict__ addend, float scale)
{
    int z = blockIdx.z;
    A += (size_t)z * sA;
    B += (size_t)z * sB;
    C += (size_t)z * sC;

    __shared__ __align__(16) float As[BK * LDST];
    __shared__ __align__(16) float Bs[BK * LDST];

    const int tid = threadIdx.x;
    const int tx = tid & 15, ty = tid >> 4;
    const int r0 = ty * 8, c0 = tx * 8;
    const int m0 = blockIdx.y * BM, n0 = blockIdx.x * BN;

    // loader mapping (transpose-style for A and NT-B)
    const int arow = tid >> 1;           // 0..127
    const int akk  = (tid & 1) * 8;      // 0 or 8
    const int bkr  = tid >> 4;           // 0..15  (NN)
    const int bn   = (tid & 15) * 8;     // 0..120 (NN)

    const float* Aptr = A + (size_t)(m0 + arow) * K + akk;
    const float* Bptr = BTRANS ? (B + (size_t)(n0 + arow) * K + akk)
                               : (B + (size_t)bkr * N + n0 + bn);

    unsigned long long acc[8][4];
    #pragma unroll
    for (int i = 0; i < 8; i++)
        #pragma unroll
        for (int p = 0; p < 4; p++) acc[i][p] = 0ull;

    const int numTiles = K / BK;

    // prefetch tile 0
    float4 pa0 = *(const float4*)(Aptr);
    float4 pa1 = *(const float4*)(Aptr + 4);
    float4 pb0 = *(const float4*)(Bptr);
    float4 pb1 = *(const float4*)(Bptr + 4);

    for (int t = 0; t < numTiles; ++t) {
        // store prefetched tile to smem
        As[(akk + 0) * LDST + arow] = pa0.x;
        As[(akk + 1) * LDST + arow] = pa0.y;
        As[(akk + 2) * LDST + arow] = pa0.z;
        As[(akk + 3) * LDST + arow] = pa0.w;
        As[(akk + 4) * LDST + arow] = pa1.x;
        As[(akk + 5) * LDST + arow] = pa1.y;
        As[(akk + 6) * LDST + arow] = pa1.z;
        As[(akk + 7) * LDST + arow] = pa1.w;
        if (BTRANS) {
            Bs[(akk + 0) * LDST + arow] = pb0.x;
            Bs[(akk + 1) * LDST + arow] = pb0.y;
            Bs[(akk + 2) * LDST + arow] = pb0.z;
            Bs[(akk + 3) * LDST + arow] = pb0.w;
            Bs[(akk + 4) * LDST + arow] = pb1.x;
            Bs[(akk + 5) * LDST + arow] = pb1.y;
            Bs[(akk + 6) * LDST + arow] = pb1.z;
            Bs[(akk + 7) * LDST + arow] = pb1.w;
        } else {
            *(float4*)&Bs[bkr * LDST + bn]     = pb0;
            *(float4*)&Bs[bkr * LDST + bn + 4] = pb1;
        }
        __syncthreads();

        // prefetch next tile (overlaps with compute below)
        if (t + 1 < numTiles) {
            Aptr += BK;
            Bptr += BTRANS ? BK : (size_t)BK * N;
            pa0 = *(const float4*)(Aptr);
            pa1 = *(const float4*)(Aptr + 4);
            pb0 = *(const float4*)(Bptr);
            pb1 = *(const float4*)(Bptr + 4);
        }

        #pragma unroll
        for (int k = 0; k < BK; k++) {
            const float* as = &As[k * LDST + r0];
            float4 a0 = *(const float4*)as;
            float4 a1 = *(const float4*)(as + 4);

            unsigned long long a2[8];
            asm("mov.b64 %0,{%1,%1};" : "=l"(a2[0]) : "f"(a0.x));
            asm("mov.b64 %0,{%1,%1};" : "=l"(a2[1]) : "f"(a0.y));
            asm("mov.b64 %0,{%1,%1};" : "=l"(a2[2]) : "f"(a0.z));
            asm("mov.b64 %0,{%1,%1};" : "=l"(a2[3]) : "f"(a0.w));
            asm("mov.b64 %0,{%1,%1};" : "=l"(a2[4]) : "f"(a1.x));
            asm("mov.b64 %0,{%1,%1};" : "=l"(a2[5]) : "f"(a1.y));
            asm("mov.b64 %0,{%1,%1};" : "=l"(a2[6]) : "f"(a1.z));
            asm("mov.b64 %0,{%1,%1};" : "=l"(a2[7]) : "f"(a1.w));

            const float* bs = &Bs[k * LDST + c0];
            unsigned long long b2[4];
            b2[0] = *(const unsigned long long*)(bs + 0);
            b2[1] = *(const unsigned long long*)(bs + 2);
            b2[2] = *(const unsigned long long*)(bs + 4);
            b2[3] = *(const unsigned long long*)(bs + 6);

            #pragma unroll
            for (int i = 0; i < 8; i++)
                #pragma unroll
                for (int p = 0; p < 4; p++)
                    asm("fma.rn.f32x2 %0,%1,%2,%0;"
                        : "+l"(acc[i][p]) : "l"(a2[i]), "l"(b2[p]));
        }
        __syncthreads();
    }

    // epilogue
    float4 bv0, bv1;
    if (EPI == 1) {
        bv0 = *(const float4*)&bias[n0 + c0];
        bv1 = *(const float4*)&bias[n0 + c0 + 4];
    }

    #pragma unroll
    for (int i = 0; i < 8; i++) {
        int row = m0 + r0 + i;
        float o[8];
        #pragma unroll
        for (int p = 0; p < 4; p++)
            asm("mov.b64 {%0,%1},%2;" : "=f"(o[2 * p]), "=f"(o[2 * p + 1]) : "l"(acc[i][p]));

        float* cp = &C[(size_t)row * N + n0 + c0];
        if (EPI == 1) {
            const float* ap = &addend[(size_t)row * N + n0 + c0];
            float4 ad0 = *(const float4*)(ap);
            float4 ad1 = *(const float4*)(ap + 4);
            float4 r0v = make_float4((o[0] + bv0.x + ad0.x) * scale,
                                     (o[1] + bv0.y + ad0.y) * scale,
                                     (o[2] + bv0.z + ad0.z) * scale,
                                     (o[3] + bv0.w + ad0.w) * scale);
            float4 r1v = make_float4((o[4] + bv1.x + ad1.x) * scale,
                                     (o[5] + bv1.y + ad1.y) * scale,
                                     (o[6] + bv1.z + ad1.z) * scale,
                                     (o[7] + bv1.w + ad1.w) * scale);
            *(float4*)(cp)     = r0v;
            *(float4*)(cp + 4) = r1v;
        } else {
            float4 r0v = make_float4(o[0] * scale, o[1] * scale, o[2] * scale, o[3] * scale);
            float4 r1v = make_float4(o[4] * scale, o[5] * scale, o[6] * scale, o[7] * scale);
            *(float4*)(cp)     = r0v;
            *(float4*)(cp + 4) = r1v;
        }
    }
}

// ---------------------------------------------------------------------------
// row softmax over S=1024, in place. One block (256 thr) per row; 4 elems/thr.
// ---------------------------------------------------------------------------
__global__ void softmax_kernel(float* __restrict__ attn)
{
    size_t row = blockIdx.x;
    float* p = attn + row * 1024;
    int tid = threadIdx.x;

    float4 v = *(const float4*)&p[tid * 4];

    __shared__ float sm[8];

    float m = fmaxf(fmaxf(v.x, v.y), fmaxf(v.z, v.w));
    #pragma unroll
    for (int o = 16; o > 0; o >>= 1) m = fmaxf(m, __shfl_xor_sync(0xffffffffu, m, o));
    if ((tid & 31) == 0) sm[tid >> 5] = m;
    __syncthreads();
    float rmax = sm[0];
    #pragma unroll
    for (int w = 1; w < 8; w++) rmax = fmaxf(rmax, sm[w]);

    float e0 = expf(v.x - rmax);
    float e1 = expf(v.y - rmax);
    float e2 = expf(v.z - rmax);
    float e3 = expf(v.w - rmax);

    float s = (e0 + e1) + (e2 + e3);
    #pragma unroll
    for (int o = 16; o > 0; o >>= 1) s += __shfl_xor_sync(0xffffffffu, s, o);
    __syncthreads();
    if ((tid & 31) == 0) sm[tid >> 5] = s;
    __syncthreads();
    float rsum = 0.f;
    #pragma unroll
    for (int w = 0; w < 8; w++) rsum += sm[w];
    float inv = 1.f / rsum;

    *(float4*)&p[tid * 4] = make_float4(e0 * inv, e1 * inv, e2 * inv, e3 * inv);
}

// ---------------------------------------------------------------------------
extern "C" void kernel_launch(void* const* d_in, const int* in_sizes, int n_in,
                              void* d_out, int out_size)
{
    const float* x     = (const float*)d_in[0];   // [64,1024,512]
    const float* te    = (const float*)d_in[1];   // [64,1024,512]
    const float* enc0  = (const float*)d_in[2];   // [64,512,1024]
    const float* enc1  = (const float*)d_in[3];   // [64,512,1024]
    const float* enc2  = (const float*)d_in[4];   // [64,1024,512]
    const float* in_v  = (const float*)d_in[5];   // [512,512]
    const float* in_g  = (const float*)d_in[6];   // [512]
    const float* in_b  = (const float*)d_in[7];   // [512]
    const float* out_v = (const float*)d_in[8];   // [512,512]
    const float* out_g = (const float*)d_in[9];   // [512]
    const float* out_b = (const float*)d_in[10];  // [512]

    float* out  = (float*)d_out;                          // [64*1024*512]
    float* attn = out + (size_t)64 * 1024 * 512;          // [64*1024*1024]

    float *h, *ctx, *esum, *win, *wout;
    cudaGetSymbolAddress((void**)&h,    g_h);
    cudaGetSymbolAddress((void**)&ctx,  g_ctx);
    cudaGetSymbolAddress((void**)&esum, g_esum);
    cudaGetSymbolAddress((void**)&win,  g_win);
    cudaGetSymbolAddress((void**)&wout, g_wout);

    dim3 blk(256);

    // normalized weights + encoder sum
    wn_kernel<<<512, 256>>>(in_v,  in_g,  win,  512);
    wn_kernel<<<512, 256>>>(out_v, out_g, wout, 512);
    esum_kernel<<<32768, 256>>>((const float4*)enc0, (const float4*)enc1, (float4*)esum);

    // K1: h = (x @ W_in^T + in_b + te) * sqrt(0.5)      M=65536 N=512 K=512 (NT)
    gemm2_kernel<true, 1><<<dim3(512 / BN, 65536 / BM, 1), blk>>>(
        x, win, h, 65536, 512, 512, 0LL, 0LL, 0LL, in_b, te, SQRT_HALF_F);

    // K2: scores = h @ esum  per batch: M=1024 N=1024 K=512 (NN)
    gemm2_kernel<false, 0><<<dim3(1024 / BN, 1024 / BM, 64), blk>>>(
        h, esum, attn, 1024, 1024, 512,
        (long long)1024 * 512, (long long)512 * 1024, (long long)1024 * 1024,
        nullptr, nullptr, 1.0f);

    // K3: softmax over S, in place in the attn output region
    softmax_kernel<<<65536, 256>>>(attn);

    // K4: ctx = (attn @ enc2) * 32  per batch: M=1024 N=512 K=1024 (NN)
    gemm2_kernel<false, 0><<<dim3(512 / BN, 1024 / BM, 64), blk>>>(
        attn, enc2, ctx, 1024, 512, 1024,
        (long long)1024 * 1024, (long long)1024 * 512, (long long)1024 * 512,
        nullptr, nullptr, 32.0f);

    // K5: out = (ctx @ W_out^T + out_b + x) * sqrt(0.5)  M=65536 N=512 K=512 (NT)
    gemm2_kernel<true, 1><<<dim3(512 / BN, 65536 / BM, 1), blk>>>(
        ctx, wout, out, 65536, 512, 512, 0LL, 0LL, 0LL, out_b, x, SQRT_HALF_F);
}

// round 4
// speedup vs baseline: 2.6961x; 2.4340x over previous
#include <cuda_runtime.h>
#include <cuda_bf16.h>
#include <math.h>
#include <stdint.h>

// ===========================================================================
// AttentionLayer via mma.sync bf16 split GEMMs (fp32 accumulate in registers)
// B=64, T=1024, S=1024, C=E=512. Output = concat(out [B,T,C], attn [B,T,S])
//
// fp32 operand x split as hi+lo bf16. GEMM over 3x-concatenated K:
//   A' = [Ahi | Alo | Ahi]   (row-major [M, 3K])
//   B' = [Bhi | Bhi | Blo]   (row-major [N, 3K], K-major rows)
//   C  = Ahi·Bhi + Alo·Bhi + Ahi·Blo  ≈ A·B  (err ~2^-17)
// ===========================================================================

static const float SQRT_HALF_F = 0.70710678118654752440f;

// ------------------------------ scratch ------------------------------------
__device__ __nv_bfloat16 g_xsplit  [(size_t)65536 * 1536];
__device__ __nv_bfloat16 g_hsplit  [(size_t)65536 * 1536];
__device__ __nv_bfloat16 g_ctxsplit[(size_t)65536 * 1536];
__device__ __nv_bfloat16 g_attnsplit[(size_t)65536 * 3072];
__device__ __nv_bfloat16 g_esumT   [(size_t)64 * 1024 * 1536];
__device__ __nv_bfloat16 g_enc2T   [(size_t)64 * 512 * 3072];
__device__ __nv_bfloat16 g_winsplit [512 * 1536];
__device__ __nv_bfloat16 g_woutsplit[512 * 1536];

// ------------------------------ helpers ------------------------------------
__device__ __forceinline__ uint32_t smem_u32(const void* p) {
    uint32_t a;
    asm("{ .reg .u64 t; cvta.to.shared.u64 t, %1; cvt.u32.u64 %0, t; }"
        : "=r"(a) : "l"(p));
    return a;
}

// pack two floats -> bf16x2 (memory order: first arg at lower address)
__device__ __forceinline__ uint32_t f2bf2(float lo, float hi) {
    uint32_t r;
    asm("cvt.rn.bf16x2.f32 %0, %1, %2;" : "=r"(r) : "f"(hi), "f"(lo));
    return r;
}
__device__ __forceinline__ float bfround(float v) {
    return __bfloat162float(__float2bfloat16(v));
}

__device__ __forceinline__ void cp16(uint32_t s, const void* g) {
    asm volatile("cp.async.cg.shared.global [%0], [%1], 16;" :: "r"(s), "l"(g));
}

__device__ __forceinline__ void ldsm4(uint32_t* r, uint32_t addr) {
    asm volatile("ldmatrix.sync.aligned.m8n8.x4.shared.b16 {%0,%1,%2,%3}, [%4];"
                 : "=r"(r[0]), "=r"(r[1]), "=r"(r[2]), "=r"(r[3]) : "r"(addr));
}

__device__ __forceinline__ void mma16816(float* d, const uint32_t* a,
                                         uint32_t b0, uint32_t b1) {
    asm volatile(
        "mma.sync.aligned.m16n8k16.row.col.f32.bf16.bf16.f32 "
        "{%0,%1,%2,%3}, {%4,%5,%6,%7}, {%8,%9}, {%0,%1,%2,%3};"
        : "+f"(d[0]), "+f"(d[1]), "+f"(d[2]), "+f"(d[3])
        : "r"(a[0]), "r"(a[1]), "r"(a[2]), "r"(a[3]), "r"(b0), "r"(b1));
}

// ===========================================================================
// weight-norm + split (B-layout [hi|hi|lo]): one block per row, cols=512
// ===========================================================================
__global__ void wn_split_kernel(const float* __restrict__ v, const float* __restrict__ g,
                                __nv_bfloat16* __restrict__ w, int cols)
{
    int r = blockIdx.x;
    int tid = threadIdx.x;
    const float* vr = v + (size_t)r * cols;

    float ss = 0.f;
    for (int c = tid; c < cols; c += blockDim.x) { float t = vr[c]; ss += t * t; }
    __shared__ float sm[32];
    #pragma unroll
    for (int o = 16; o > 0; o >>= 1) ss += __shfl_down_sync(0xffffffffu, ss, o);
    int warp = tid >> 5, lane = tid & 31;
    if (lane == 0) sm[warp] = ss;
    __syncthreads();
    int nw = blockDim.x >> 5;
    if (warp == 0) {
        float s2 = (lane < nw) ? sm[lane] : 0.f;
        #pragma unroll
        for (int o = 16; o > 0; o >>= 1) s2 += __shfl_down_sync(0xffffffffu, s2, o);
        if (lane == 0) sm[0] = s2;
    }
    __syncthreads();
    float scale = g[r] / sqrtf(sm[0]);
    __nv_bfloat16* wr = w + (size_t)r * (3 * cols);
    for (int c = tid; c < cols; c += blockDim.x) {
        float wv = vr[c] * scale;
        __nv_bfloat16 h = __float2bfloat16(wv);
        __nv_bfloat16 l = __float2bfloat16(wv - __bfloat162float(h));
        wr[c] = h;
        wr[cols + c] = h;
        wr[2 * cols + c] = l;
    }
}

// ===========================================================================
// A-split (no transpose, [hi|lo|hi]):  x [65536,512] -> [65536,1536]
// ===========================================================================
__global__ void asplit_kernel(const float* __restrict__ in, __nv_bfloat16* __restrict__ out)
{
    size_t idx = (size_t)blockIdx.x * 256 + threadIdx.x;
    size_t row = idx >> 6;
    int g = (int)(idx & 63);
    const float* p = in + row * 512 + g * 8;
    float4 f0 = *(const float4*)p;
    float4 f1 = *(const float4*)(p + 4);
    float v[8] = {f0.x, f0.y, f0.z, f0.w, f1.x, f1.y, f1.z, f1.w};
    uint32_t hi[4], lo[4];
    #pragma unroll
    for (int q = 0; q < 4; q++) {
        hi[q] = f2bf2(v[2*q], v[2*q+1]);
        lo[q] = f2bf2(v[2*q] - bfround(v[2*q]), v[2*q+1] - bfround(v[2*q+1]));
    }
    __nv_bfloat16* o = out + row * 1536 + g * 8;
    *(uint4*)(o)        = *(uint4*)hi;   // sec0 hi
    *(uint4*)(o + 512)  = *(uint4*)lo;   // sec1 lo
    *(uint4*)(o + 1024) = *(uint4*)hi;   // sec2 hi
}

// ===========================================================================
// transpose + split (B-layout [hi|hi|lo]):
//   in (optionally in0+in1) is [R, Cc] per batch -> out [Cc, 3R]
// ===========================================================================
__global__ void transpose_split_kernel(const float* __restrict__ in0,
                                       const float* __restrict__ in1,
                                       __nv_bfloat16* __restrict__ out,
                                       int R, int Cc, long long sIn, long long sOut)
{
    __shared__ float tile[64][33];
    int b = blockIdx.z;
    const float* A0 = in0 + (size_t)b * sIn;
    const float* A1 = in1 ? in1 + (size_t)b * sIn : nullptr;
    __nv_bfloat16* O = out + (size_t)b * sOut;
    int r0 = blockIdx.x * 64;
    int c0 = blockIdx.y * 32;
    int tid = threadIdx.x;

    #pragma unroll
    for (int i = 0; i < 8; i++) {
        int idx = i * 256 + tid;
        int rr = idx >> 5, cc = idx & 31;
        size_t off = (size_t)(r0 + rr) * Cc + c0 + cc;
        float vv = A0[off];
        if (A1) vv += A1[off];
        tile[rr][cc] = vv;
    }
    __syncthreads();

    int j = tid >> 3;
    int g = tid & 7;
    float v[8];
    #pragma unroll
    for (int u = 0; u < 8; u++) v[u] = tile[g * 8 + u][j];
    uint32_t hi[4], lo[4];
    #pragma unroll
    for (int p = 0; p < 4; p++) {
        hi[p] = f2bf2(v[2*p], v[2*p+1]);
        lo[p] = f2bf2(v[2*p] - bfround(v[2*p]), v[2*p+1] - bfround(v[2*p+1]));
    }
    __nv_bfloat16* ob = O + (size_t)(c0 + j) * (3 * R) + r0 + g * 8;
    *(uint4*)(ob)         = *(uint4*)hi;   // sec0 hi
    *(uint4*)(ob + R)     = *(uint4*)hi;   // sec1 hi
    *(uint4*)(ob + 2 * R) = *(uint4*)lo;   // sec2 lo
}

// ===========================================================================
// mma.sync GEMM: C[128x128] = A'[M,K3] x B'[N,K3]^T, fp32 accum.
// 256 thr = 8 warps (4m x 2n), warp tile m32 x n64, chunk = 64 bf16 of K.
// EPI: 0 = f32 C=acc*scale ; 1 = f32 C=(acc+bias+addend)*scale
//      2 = split-A-layout C=acc*scale ; 3 = split-A-layout (acc+bias+addend)*scale
// ===========================================================================
#define SMEM_BYTES 65536

template <int EPI>
__global__ __launch_bounds__(256)
void mma_gemm(const __nv_bfloat16* __restrict__ A,
              const __nv_bfloat16* __restrict__ B,
              float* __restrict__ Cf, __nv_bfloat16* __restrict__ Cs,
              int N, int K3,
              long long sA, long long sB, long long sC,
              const float* __restrict__ bias,
              const float* __restrict__ addend,
              float scale)
{
    extern __shared__ __align__(1024) char smem[];
    uint32_t sbase = smem_u32(smem);
    const uint32_t Ab[2] = { sbase,         sbase + 16384 };
    const uint32_t Bb[2] = { sbase + 32768, sbase + 49152 };

    int tid = threadIdx.x, wid = tid >> 5, lane = tid & 31;
    int z = blockIdx.z;
    A += (size_t)z * sA;
    B += (size_t)z * sB;
    if (EPI <= 1) Cf += (size_t)z * sC; else Cs += (size_t)z * sC;
    int m0 = blockIdx.y * 128, n0 = blockIdx.x * 128;
    int warpM = (wid >> 1) * 32, warpN = (wid & 1) * 64;

    // ---- loader mapping: 8x16B cp.async per (A,B) pair per chunk ----
    int c = tid & 7, rbase = tid >> 3;
    const size_t rs = (size_t)32 * K3 * 2;   // 32 rows in bytes
    const char* aP = (const char*)(A + (size_t)(m0 + rbase) * K3 + c * 8);
    const char* bP = (const char*)(B + (size_t)(n0 + rbase) * K3 + c * 8);
    uint32_t swo[4];
    #pragma unroll
    for (int i = 0; i < 4; i++) {
        uint32_t bo = (uint32_t)(rbase + 32 * i) * 128 + c * 16;
        swo[i] = bo ^ ((bo >> 3) & 0x70);
    }

#define LOADCHUNK(ABUF, BBUF, KOFF) do {                                   \
        const char* ag_ = aP + (size_t)(KOFF);                             \
        const char* bg_ = bP + (size_t)(KOFF);                             \
        cp16((ABUF) + swo[0], ag_);            cp16((BBUF) + swo[0], bg_); \
        cp16((ABUF) + swo[1], ag_ + rs);       cp16((BBUF) + swo[1], bg_ + rs); \
        cp16((ABUF) + swo[2], ag_ + 2 * rs);   cp16((BBUF) + swo[2], bg_ + 2 * rs); \
        cp16((ABUF) + swo[3], ag_ + 3 * rs);   cp16((BBUF) + swo[3], bg_ + 3 * rs); \
        asm volatile("cp.async.commit_group;" ::: "memory");               \
    } while (0)

    // ---- ldmatrix per-lane swizzled offsets (col-ks XORs in later) ----
    // A fragment x4: lanes 0-15 rows m+(l&15) col 0 ; lanes 16-31 same rows col +16B
    uint32_t aoff[2], boff[4];
    {
        int l = lane;
        #pragma unroll
        for (int mt = 0; mt < 2; mt++) {
            int row = warpM + mt * 16 + (l & 15);
            uint32_t cb = (uint32_t)((l >> 4) << 4);
            aoff[mt] = (uint32_t)row * 128 + (cb ^ (((uint32_t)row & 7) << 4));
        }
        #pragma unroll
        for (int ng = 0; ng < 4; ng++) {
            int row = warpN + ng * 16 + (l & 7) + ((l >> 4) << 3);
            uint32_t cb = (uint32_t)(((l >> 3) & 1) << 4);
            boff[ng] = (uint32_t)row * 128 + (cb ^ (((uint32_t)row & 7) << 4));
        }
    }

    float d[2][8][4];
    #pragma unroll
    for (int mt = 0; mt < 2; mt++)
        #pragma unroll
        for (int nt = 0; nt < 8; nt++)
            #pragma unroll
            for (int q = 0; q < 4; q++) d[mt][nt][q] = 0.f;

    const int numK = K3 >> 6;
    LOADCHUNK(Ab[0], Bb[0], 0);

    for (int ck = 0; ck < numK; ck++) {
        int buf = ck & 1;
        if (ck + 1 < numK) {
            int ob = buf ^ 1;
            LOADCHUNK(Ab[ob], Bb[ob], (size_t)(ck + 1) * 128);
            asm volatile("cp.async.wait_group 1;" ::: "memory");
        } else {
            asm volatile("cp.async.wait_group 0;" ::: "memory");
        }
        __syncthreads();

        uint32_t ab = Ab[buf], bb = Bb[buf];
        #pragma unroll
        for (int ks = 0; ks < 4; ks++) {
            uint32_t kx = (uint32_t)ks << 5;
            uint32_t a[2][4];
            ldsm4(a[0], ab + (aoff[0] ^ kx));
            ldsm4(a[1], ab + (aoff[1] ^ kx));
            #pragma unroll
            for (int ng = 0; ng < 4; ng++) {
                uint32_t bq[4];
                ldsm4(bq, bb + (boff[ng] ^ kx));
                #pragma unroll
                for (int mt = 0; mt < 2; mt++) {
                    mma16816(d[mt][2 * ng],     a[mt], bq[0], bq[1]);
                    mma16816(d[mt][2 * ng + 1], a[mt], bq[2], bq[3]);
                }
            }
        }
        __syncthreads();
    }
#undef LOADCHUNK

    // ---- epilogue ----
    int trow = lane >> 2, tcol = (lane & 3) * 2;
    #pragma unroll
    for (int mt = 0; mt < 2; mt++) {
        #pragma unroll
        for (int rr = 0; rr < 2; rr++) {
            size_t grow = (size_t)(m0 + warpM + mt * 16 + trow + rr * 8);
            #pragma unroll
            for (int nt = 0; nt < 8; nt++) {
                int gcol = n0 + warpN + nt * 8 + tcol;
                float v0 = d[mt][nt][rr * 2 + 0];
                float v1 = d[mt][nt][rr * 2 + 1];
                if (EPI == 1 || EPI == 3) {
                    float2 bq = *(const float2*)(bias + gcol);
                    float2 aq = *(const float2*)(addend + grow * N + gcol);
                    v0 = (v0 + bq.x + aq.x) * scale;
                    v1 = (v1 + bq.y + aq.y) * scale;
                } else {
                    v0 *= scale; v1 *= scale;
                }
                if (EPI <= 1) {
                    *(float2*)(Cf + grow * N + gcol) = make_float2(v0, v1);
                } else {
                    __nv_bfloat16* o = Cs + grow * (size_t)(3 * N) + gcol;
                    uint32_t hi = f2bf2(v0, v1);
                    uint32_t lo = f2bf2(v0 - bfround(v0), v1 - bfround(v1));
                    *(uint32_t*)(o)         = hi;   // sec0 hi
                    *(uint32_t*)(o + N)     = lo;   // sec1 lo
                    *(uint32_t*)(o + 2 * N) = hi;   // sec2 hi
                }
            }
        }
    }
}

// ===========================================================================
// softmax over S=1024, in place; also emits split-A-layout bf16 copy
// ===========================================================================
__global__ void softmax_split_kernel(float* __restrict__ attn,
                                     __nv_bfloat16* __restrict__ asp)
{
    size_t row = blockIdx.x;
    float* p = attn + row * 1024;
    int tid = threadIdx.x;

    float4 v = *(const float4*)&p[tid * 4];
    __shared__ float sm[8];

    float m = fmaxf(fmaxf(v.x, v.y), fmaxf(v.z, v.w));
    #pragma unroll
    for (int o = 16; o > 0; o >>= 1) m = fmaxf(m, __shfl_xor_sync(0xffffffffu, m, o));
    if ((tid & 31) == 0) sm[tid >> 5] = m;
    __syncthreads();
    float rmax = sm[0];
    #pragma unroll
    for (int w = 1; w < 8; w++) rmax = fmaxf(rmax, sm[w]);

    float e0 = expf(v.x - rmax), e1 = expf(v.y - rmax);
    float e2 = expf(v.z - rmax), e3 = expf(v.w - rmax);

    float s = (e0 + e1) + (e2 + e3);
    #pragma unroll
    for (int o = 16; o > 0; o >>= 1) s += __shfl_xor_sync(0xffffffffu, s, o);
    __syncthreads();
    if ((tid & 31) == 0) sm[tid >> 5] = s;
    __syncthreads();
    float rsum = 0.f;
    #pragma unroll
    for (int w = 0; w < 8; w++) rsum += sm[w];
    float inv = 1.f / rsum;

    float o0 = e0 * inv, o1 = e1 * inv, o2 = e2 * inv, o3 = e3 * inv;
    *(float4*)&p[tid * 4] = make_float4(o0, o1, o2, o3);

    uint32_t hi[2], lo[2];
    hi[0] = f2bf2(o0, o1);
    hi[1] = f2bf2(o2, o3);
    lo[0] = f2bf2(o0 - bfround(o0), o1 - bfround(o1));
    lo[1] = f2bf2(o2 - bfround(o2), o3 - bfround(o3));
    __nv_bfloat16* ob = asp + row * 3072 + tid * 4;
    *(uint2*)(ob)        = *(uint2*)hi;   // sec0 hi
    *(uint2*)(ob + 1024) = *(uint2*)lo;   // sec1 lo
    *(uint2*)(ob + 2048) = *(uint2*)hi;   // sec2 hi
}

// ===========================================================================
extern "C" void kernel_launch(void* const* d_in, const int* in_sizes, int n_in,
                              void* d_out, int out_size)
{
    const float* x     = (const float*)d_in[0];
    const float* te    = (const float*)d_in[1];
    const float* enc0  = (const float*)d_in[2];
    const float* enc1  = (const float*)d_in[3];
    const float* enc2  = (const float*)d_in[4];
    const float* in_v  = (const float*)d_in[5];
    const float* in_g  = (const float*)d_in[6];
    const float* in_b  = (const float*)d_in[7];
    const float* out_v = (const float*)d_in[8];
    const float* out_g = (const float*)d_in[9];
    const float* out_b = (const float*)d_in[10];

    float* out  = (float*)d_out;
    float* attn = out + (size_t)64 * 1024 * 512;

    __nv_bfloat16 *xsp, *hsp, *ctxsp, *attnsp, *esumT, *enc2T, *winsp, *woutsp;
    cudaGetSymbolAddress((void**)&xsp,    g_xsplit);
    cudaGetSymbolAddress((void**)&hsp,    g_hsplit);
    cudaGetSymbolAddress((void**)&ctxsp,  g_ctxsplit);
    cudaGetSymbolAddress((void**)&attnsp, g_attnsplit);
    cudaGetSymbolAddress((void**)&esumT,  g_esumT);
    cudaGetSymbolAddress((void**)&enc2T,  g_enc2T);
    cudaGetSymbolAddress((void**)&winsp,  g_winsplit);
    cudaGetSymbolAddress((void**)&woutsp, g_woutsplit);

    cudaFuncSetAttribute(mma_gemm<0>, cudaFuncAttributeMaxDynamicSharedMemorySize, SMEM_BYTES);
    cudaFuncSetAttribute(mma_gemm<1>, cudaFuncAttributeMaxDynamicSharedMemorySize, SMEM_BYTES);
    cudaFuncSetAttribute(mma_gemm<2>, cudaFuncAttributeMaxDynamicSharedMemorySize, SMEM_BYTES);
    cudaFuncSetAttribute(mma_gemm<3>, cudaFuncAttributeMaxDynamicSharedMemorySize, SMEM_BYTES);

    // ---- operand preparation ----
    wn_split_kernel<<<512, 256>>>(in_v,  in_g,  winsp,  512);
    wn_split_kernel<<<512, 256>>>(out_v, out_g, woutsp, 512);
    asplit_kernel<<<16384, 256>>>(x, xsp);
    transpose_split_kernel<<<dim3(8, 32, 64), 256>>>(
        enc0, enc1, esumT, 512, 1024, (long long)512 * 1024, (long long)1024 * 1536);
    transpose_split_kernel<<<dim3(16, 16, 64), 256>>>(
        enc2, nullptr, enc2T, 1024, 512, (long long)1024 * 512, (long long)512 * 3072);

    // K1: h = (x@Win^T + b + te)*sqrt(.5) -> hsplit   M=65536 N=512 K3=1536
    mma_gemm<3><<<dim3(4, 512, 1), 256, SMEM_BYTES>>>(
        xsp, winsp, nullptr, hsp, 512, 1536, 0LL, 0LL, 0LL, in_b, te, SQRT_HALF_F);

    // K2: scores = h @ esum   per batch M=1024 N=1024 K3=1536 -> attn (f32)
    mma_gemm<0><<<dim3(8, 8, 64), 256, SMEM_BYTES>>>(
        hsp, esumT, attn, nullptr, 1024, 1536,
        (long long)1024 * 1536, (long long)1024 * 1536, (long long)1024 * 1024,
        nullptr, nullptr, 1.0f);

    // K3: softmax + split
    softmax_split_kernel<<<65536, 256>>>(attn, attnsp);

    // K4: ctx = (attn @ enc2)*32 -> ctxsplit   per batch M=1024 N=512 K3=3072
    mma_gemm<2><<<dim3(4, 8, 64), 256, SMEM_BYTES>>>(
        attnsp, enc2T, nullptr, ctxsp, 512, 3072,
        (long long)1024 * 3072, (long long)512 * 3072, (long long)1024 * 1536,
        nullptr, nullptr, 32.0f);

    // K5: out = (ctx@Wout^T + b + x)*sqrt(.5)  M=65536 N=512 K3=1536 (f32)
    mma_gemm<1><<<dim3(4, 512, 1), 256, SMEM_BYTES>>>(
        ctxsp, woutsp, out, nullptr, 512, 1536, 0LL, 0LL, 0LL, out_b, x, SQRT_HALF_F);
}

// round 5
// speedup vs baseline: 2.9237x; 1.0844x over previous
#include <cuda_runtime.h>
#include <cuda_bf16.h>
#include <math.h>
#include <stdint.h>

// ===========================================================================
// AttentionLayer via mma.sync bf16 split GEMMs (fp32 accumulate in registers)
// B=64, T=1024, S=1024, C=E=512. Output = concat(out [B,T,C], attn [B,T,S])
//
// fp32 operand x split hi+lo bf16, stored [hi|lo] (2K columns). GEMM runs a
// 3-section logical K (sections remapped by the loader):
//   secs A: hi, lo, hi   secs B: hi, hi, lo
//   C = Ahi·Bhi + Alo·Bhi + Ahi·Blo  ≈ A·B  (err ~2^-18)
// ===========================================================================

static const float SQRT_HALF_F = 0.70710678118654752440f;

// ------------------------------ scratch ------------------------------------
__device__ __nv_bfloat16 g_xsplit  [(size_t)65536 * 1024];
__device__ __nv_bfloat16 g_hsplit  [(size_t)65536 * 1024];
__device__ __nv_bfloat16 g_ctxsplit[(size_t)65536 * 1024];
__device__ __nv_bfloat16 g_attnsplit[(size_t)65536 * 2048];
__device__ __nv_bfloat16 g_esumT   [(size_t)64 * 1024 * 1024];
__device__ __nv_bfloat16 g_enc2T   [(size_t)64 * 512 * 2048];
__device__ __nv_bfloat16 g_winsplit [512 * 1024];
__device__ __nv_bfloat16 g_woutsplit[512 * 1024];

// ------------------------------ helpers ------------------------------------
__device__ __forceinline__ uint32_t smem_u32(const void* p) {
    uint32_t a;
    asm("{ .reg .u64 t; cvta.to.shared.u64 t, %1; cvt.u32.u64 %0, t; }"
        : "=r"(a) : "l"(p));
    return a;
}

// pack two floats -> bf16x2 (first arg at lower address)
__device__ __forceinline__ uint32_t f2bf2(float lo, float hi) {
    uint32_t r;
    asm("cvt.rn.bf16x2.f32 %0, %1, %2;" : "=r"(r) : "f"(hi), "f"(lo));
    return r;
}
__device__ __forceinline__ float bfround(float v) {
    return __bfloat162float(__float2bfloat16(v));
}

__device__ __forceinline__ void cp16(uint32_t s, const void* g) {
    asm volatile("cp.async.cg.shared.global [%0], [%1], 16;" :: "r"(s), "l"(g));
}

__device__ __forceinline__ void ldsm4(uint32_t* r, uint32_t addr) {
    asm volatile("ldmatrix.sync.aligned.m8n8.x4.shared.b16 {%0,%1,%2,%3}, [%4];"
                 : "=r"(r[0]), "=r"(r[1]), "=r"(r[2]), "=r"(r[3]) : "r"(addr));
}

__device__ __forceinline__ void mma16816(float* d, const uint32_t* a,
                                         uint32_t b0, uint32_t b1) {
    asm volatile(
        "mma.sync.aligned.m16n8k16.row.col.f32.bf16.bf16.f32 "
        "{%0,%1,%2,%3}, {%4,%5,%6,%7}, {%8,%9}, {%0,%1,%2,%3};"
        : "+f"(d[0]), "+f"(d[1]), "+f"(d[2]), "+f"(d[3])
        : "r"(a[0]), "r"(a[1]), "r"(a[2]), "r"(a[3]), "r"(b0), "r"(b1));
}

// ===========================================================================
// weight-norm + split [hi|lo]: one block per row, cols=512
// ===========================================================================
__global__ void wn_split_kernel(const float* __restrict__ v, const float* __restrict__ g,
                                __nv_bfloat16* __restrict__ w, int cols)
{
    int r = blockIdx.x;
    int tid = threadIdx.x;
    const float* vr = v + (size_t)r * cols;

    float ss = 0.f;
    for (int c = tid; c < cols; c += blockDim.x) { float t = vr[c]; ss += t * t; }
    __shared__ float sm[32];
    #pragma unroll
    for (int o = 16; o > 0; o >>= 1) ss += __shfl_down_sync(0xffffffffu, ss, o);
    int warp = tid >> 5, lane = tid & 31;
    if (lane == 0) sm[warp] = ss;
    __syncthreads();
    int nw = blockDim.x >> 5;
    if (warp == 0) {
        float s2 = (lane < nw) ? sm[lane] : 0.f;
        #pragma unroll
        for (int o = 16; o > 0; o >>= 1) s2 += __shfl_down_sync(0xffffffffu, s2, o);
        if (lane == 0) sm[0] = s2;
    }
    __syncthreads();
    float scale = g[r] / sqrtf(sm[0]);
    __nv_bfloat16* wr = w + (size_t)r * (2 * cols);
    for (int c = tid; c < cols; c += blockDim.x) {
        float wv = vr[c] * scale;
        __nv_bfloat16 h = __float2bfloat16(wv);
        __nv_bfloat16 l = __float2bfloat16(wv - __bfloat162float(h));
        wr[c] = h;
        wr[cols + c] = l;
    }
}

// ===========================================================================
// A-split [hi|lo]:  x [65536,512] -> [65536,1024]
// ===========================================================================
__global__ void asplit_kernel(const float* __restrict__ in, __nv_bfloat16* __restrict__ out)
{
    size_t idx = (size_t)blockIdx.x * 256 + threadIdx.x;
    size_t row = idx >> 6;
    int g = (int)(idx & 63);
    const float* p = in + row * 512 + g * 8;
    float4 f0 = *(const float4*)p;
    float4 f1 = *(const float4*)(p + 4);
    float v[8] = {f0.x, f0.y, f0.z, f0.w, f1.x, f1.y, f1.z, f1.w};
    uint32_t hi[4], lo[4];
    #pragma unroll
    for (int q = 0; q < 4; q++) {
        hi[q] = f2bf2(v[2*q], v[2*q+1]);
        lo[q] = f2bf2(v[2*q] - bfround(v[2*q]), v[2*q+1] - bfround(v[2*q+1]));
    }
    __nv_bfloat16* o = out + row * 1024 + g * 8;
    *(uint4*)(o)       = *(uint4*)hi;
    *(uint4*)(o + 512) = *(uint4*)lo;
}

// ===========================================================================
// transpose + split [hi|lo]: in (optionally in0+in1) [R, Cc] -> out [Cc, 2R]
// ===========================================================================
__global__ void transpose_split_kernel(const float* __restrict__ in0,
                                       const float* __restrict__ in1,
                                       __nv_bfloat16* __restrict__ out,
                                       int R, int Cc, long long sIn, long long sOut)
{
    __shared__ float tile[64][33];
    int b = blockIdx.z;
    const float* A0 = in0 + (size_t)b * sIn;
    const float* A1 = in1 ? in1 + (size_t)b * sIn : nullptr;
    __nv_bfloat16* O = out + (size_t)b * sOut;
    int r0 = blockIdx.x * 64;
    int c0 = blockIdx.y * 32;
    int tid = threadIdx.x;

    #pragma unroll
    for (int i = 0; i < 8; i++) {
        int idx = i * 256 + tid;
        int rr = idx >> 5, cc = idx & 31;
        size_t off = (size_t)(r0 + rr) * Cc + c0 + cc;
        float vv = A0[off];
        if (A1) vv += A1[off];
        tile[rr][cc] = vv;
    }
    __syncthreads();

    int j = tid >> 3;
    int g = tid & 7;
    float v[8];
    #pragma unroll
    for (int u = 0; u < 8; u++) v[u] = tile[g * 8 + u][j];
    uint32_t hi[4], lo[4];
    #pragma unroll
    for (int p = 0; p < 4; p++) {
        hi[p] = f2bf2(v[2*p], v[2*p+1]);
        lo[p] = f2bf2(v[2*p] - bfround(v[2*p]), v[2*p+1] - bfround(v[2*p+1]));
    }
    __nv_bfloat16* ob = O + (size_t)(c0 + j) * (2 * R) + r0 + g * 8;
    *(uint4*)(ob)     = *(uint4*)hi;
    *(uint4*)(ob + R) = *(uint4*)lo;
}

// ===========================================================================
// mma.sync GEMM: C[128x128] = A x B^T over 3 remapped K-sections, fp32 accum.
// A stored [M, 2*KLOG] as [hi|lo]; B stored [N, 2*KLOG] as [hi|lo].
// Section maps: A {hi,lo,hi}, B {hi,hi,lo}. 3-stage cp.async pipeline.
// EPI: 0 = f32 C=acc*scale ; 1 = f32 C=(acc+bias+addend)*scale
//      2 = split [hi|lo] C=acc*scale ; 3 = split (acc+bias+addend)*scale
// ===========================================================================
#define SMEM_BYTES 98304

template <int EPI, int KLOG>
__global__ __launch_bounds__(256, 2)
void mma_gemm(const __nv_bfloat16* __restrict__ A,
              const __nv_bfloat16* __restrict__ B,
              float* __restrict__ Cf, __nv_bfloat16* __restrict__ Cs,
              int N,
              long long sA, long long sB, long long sC,
              const float* __restrict__ bias,
              const float* __restrict__ addend,
              float scale)
{
    constexpr int K2E    = 2 * KLOG;       // stored row length (elements)
    constexpr int SECLEN = KLOG / 64;      // chunks per section
    constexpr int NUMK   = 3 * SECLEN;

    extern __shared__ __align__(1024) char smem[];
    uint32_t sbase = smem_u32(smem);
    const uint32_t st0 = sbase, st1 = sbase + 32768, st2 = sbase + 65536;

    int tid = threadIdx.x, wid = tid >> 5, lane = tid & 31;
    int z = blockIdx.z;
    A += (size_t)z * sA;
    B += (size_t)z * sB;
    if (EPI <= 1) Cf += (size_t)z * sC; else Cs += (size_t)z * sC;
    int m0 = blockIdx.y * 128, n0 = blockIdx.x * 128;
    int warpM = (wid >> 1) * 32, warpN = (wid & 1) * 64;

    // ---- loader mapping: 4x16B cp.async per operand per chunk ----
    int c = tid & 7, rbase = tid >> 3;
    const size_t rs = (size_t)32 * K2E * 2;   // 32 rows in bytes
    const char* aRow = (const char*)(A + (size_t)(m0 + rbase) * K2E + c * 8);
    const char* bRow = (const char*)(B + (size_t)(n0 + rbase) * K2E + c * 8);
    uint32_t swo[4];
    #pragma unroll
    for (int i = 0; i < 4; i++) {
        uint32_t bo = (uint32_t)(rbase + 32 * i) * 128 + c * 16;
        swo[i] = bo ^ ((bo >> 3) & 0x70);
    }

    // per-chunk byte offsets via section remap
    auto koffA = [](int ck) -> size_t {
        int sec = ck / SECLEN;
        int kk  = ck - sec * SECLEN;
        int map = (sec == 1) ? 1 : 0;          // A: hi, lo, hi
        return ((size_t)map * KLOG + (size_t)kk * 64) * 2;
    };
    auto koffB = [](int ck) -> size_t {
        int sec = ck / SECLEN;
        int kk  = ck - sec * SECLEN;
        int map = (sec == 2) ? 1 : 0;          // B: hi, hi, lo
        return ((size_t)map * KLOG + (size_t)kk * 64) * 2;
    };

#define LOADCHUNK(STG, CK) do {                                            \
        size_t oa_ = koffA(CK), ob_ = koffB(CK);                           \
        uint32_t ab_ = (STG), bb_ = (STG) + 16384;                         \
        cp16(ab_ + swo[0], aRow + oa_);                                    \
        cp16(ab_ + swo[1], aRow + oa_ + rs);                               \
        cp16(ab_ + swo[2], aRow + oa_ + 2 * rs);                           \
        cp16(ab_ + swo[3], aRow + oa_ + 3 * rs);                           \
        cp16(bb_ + swo[0], bRow + ob_);                                    \
        cp16(bb_ + swo[1], bRow + ob_ + rs);                               \
        cp16(bb_ + swo[2], bRow + ob_ + 2 * rs);                           \
        cp16(bb_ + swo[3], bRow + ob_ + 3 * rs);                           \
        asm volatile("cp.async.commit_group;" ::: "memory");               \
    } while (0)

    // ---- ldmatrix per-lane swizzled offsets ----
    uint32_t aoff[2], boff[4];
    {
        int l = lane;
        #pragma unroll
        for (int mt = 0; mt < 2; mt++) {
            int row = warpM + mt * 16 + (l & 15);
            uint32_t cb = (uint32_t)((l >> 4) << 4);
            aoff[mt] = (uint32_t)row * 128 + (cb ^ (((uint32_t)row & 7) << 4));
        }
        #pragma unroll
        for (int ng = 0; ng < 4; ng++) {
            int row = warpN + ng * 16 + (l & 7) + ((l >> 4) << 3);
            uint32_t cb = (uint32_t)(((l >> 3) & 1) << 4);
            boff[ng] = (uint32_t)row * 128 + (cb ^ (((uint32_t)row & 7) << 4));
        }
    }

    float d[2][8][4];
    #pragma unroll
    for (int mt = 0; mt < 2; mt++)
        #pragma unroll
        for (int nt = 0; nt < 8; nt++)
            #pragma unroll
            for (int q = 0; q < 4; q++) d[mt][nt][q] = 0.f;

    // prologue: chunks 0,1 into stages 0,1
    LOADCHUNK(st0, 0);
    LOADCHUNK(st1, 1);

    uint32_t stage[3] = { st0, st1, st2 };
    int cur = 0, nxt = 2;   // stage index for compute / for next load

    for (int ck = 0; ck < NUMK; ck++) {
        if (ck < NUMK - 1) asm volatile("cp.async.wait_group 1;" ::: "memory");
        else               asm volatile("cp.async.wait_group 0;" ::: "memory");
        __syncthreads();

        if (ck + 2 < NUMK) {
            LOADCHUNK(stage[nxt], ck + 2);
            nxt = (nxt == 2) ? 0 : nxt + 1;
        }

        uint32_t ab = stage[cur], bb = stage[cur] + 16384;
        cur = (cur == 2) ? 0 : cur + 1;
        #pragma unroll
        for (int ks = 0; ks < 4; ks++) {
            uint32_t kx = (uint32_t)ks << 5;
            uint32_t a[2][4];
            ldsm4(a[0], ab + (aoff[0] ^ kx));
            ldsm4(a[1], ab + (aoff[1] ^ kx));
            #pragma unroll
            for (int ng = 0; ng < 4; ng++) {
                uint32_t bq[4];
                ldsm4(bq, bb + (boff[ng] ^ kx));
                #pragma unroll
                for (int mt = 0; mt < 2; mt++) {
                    mma16816(d[mt][2 * ng],     a[mt], bq[0], bq[1]);
                    mma16816(d[mt][2 * ng + 1], a[mt], bq[2], bq[3]);
                }
            }
        }
    }
#undef LOADCHUNK

    // ---- epilogue ----
    int trow = lane >> 2, tcol = (lane & 3) * 2;
    #pragma unroll
    for (int mt = 0; mt < 2; mt++) {
        #pragma unroll
        for (int rr = 0; rr < 2; rr++) {
            size_t grow = (size_t)(m0 + warpM + mt * 16 + trow + rr * 8);
            #pragma unroll
            for (int nt = 0; nt < 8; nt++) {
                int gcol = n0 + warpN + nt * 8 + tcol;
                float v0 = d[mt][nt][rr * 2 + 0];
                float v1 = d[mt][nt][rr * 2 + 1];
                if (EPI == 1 || EPI == 3) {
                    float2 bq = *(const float2*)(bias + gcol);
                    float2 aq = *(const float2*)(addend + grow * N + gcol);
                    v0 = (v0 + bq.x + aq.x) * scale;
                    v1 = (v1 + bq.y + aq.y) * scale;
                } else {
                    v0 *= scale; v1 *= scale;
                }
                if (EPI <= 1) {
                    *(float2*)(Cf + grow * N + gcol) = make_float2(v0, v1);
                } else {
                    __nv_bfloat16* o = Cs + grow * (size_t)(2 * N) + gcol;
                    uint32_t hi = f2bf2(v0, v1);
                    uint32_t lo = f2bf2(v0 - bfround(v0), v1 - bfround(v1));
                    *(uint32_t*)(o)     = hi;
                    *(uint32_t*)(o + N) = lo;
                }
            }
        }
    }
}

// ===========================================================================
// softmax over S=1024, in place; also emits split [hi|lo] bf16 copy
// ===========================================================================
__global__ void softmax_split_kernel(float* __restrict__ attn,
                                     __nv_bfloat16* __restrict__ asp)
{
    size_t row = blockIdx.x;
    float* p = attn + row * 1024;
    int tid = threadIdx.x;

    float4 v = *(const float4*)&p[tid * 4];
    __shared__ float sm[8];

    float m = fmaxf(fmaxf(v.x, v.y), fmaxf(v.z, v.w));
    #pragma unroll
    for (int o = 16; o > 0; o >>= 1) m = fmaxf(m, __shfl_xor_sync(0xffffffffu, m, o));
    if ((tid & 31) == 0) sm[tid >> 5] = m;
    __syncthreads();
    float rmax = sm[0];
    #pragma unroll
    for (int w = 1; w < 8; w++) rmax = fmaxf(rmax, sm[w]);

    float e0 = expf(v.x - rmax), e1 = expf(v.y - rmax);
    float e2 = expf(v.z - rmax), e3 = expf(v.w - rmax);

    float s = (e0 + e1) + (e2 + e3);
    #pragma unroll
    for (int o = 16; o > 0; o >>= 1) s += __shfl_xor_sync(0xffffffffu, s, o);
    __syncthreads();
    if ((tid & 31) == 0) sm[tid >> 5] = s;
    __syncthreads();
    float rsum = 0.f;
    #pragma unroll
    for (int w = 0; w < 8; w++) rsum += sm[w];
    float inv = 1.f / rsum;

    float o0 = e0 * inv, o1 = e1 * inv, o2 = e2 * inv, o3 = e3 * inv;
    *(float4*)&p[tid * 4] = make_float4(o0, o1, o2, o3);

    uint32_t hi[2], lo[2];
    hi[0] = f2bf2(o0, o1);
    hi[1] = f2bf2(o2, o3);
    lo[0] = f2bf2(o0 - bfround(o0), o1 - bfround(o1));
    lo[1] = f2bf2(o2 - bfround(o2), o3 - bfround(o3));
    __nv_bfloat16* ob = asp + row * 2048 + tid * 4;
    *(uint2*)(ob)        = *(uint2*)hi;
    *(uint2*)(ob + 1024) = *(uint2*)lo;
}

// ===========================================================================
extern "C" void kernel_launch(void* const* d_in, const int* in_sizes, int n_in,
                              void* d_out, int out_size)
{
    const float* x     = (const float*)d_in[0];
    const float* te    = (const float*)d_in[1];
    const float* enc0  = (const float*)d_in[2];
    const float* enc1  = (const float*)d_in[3];
    const float* enc2  = (const float*)d_in[4];
    const float* in_v  = (const float*)d_in[5];
    const float* in_g  = (const float*)d_in[6];
    const float* in_b  = (const float*)d_in[7];
    const float* out_v = (const float*)d_in[8];
    const float* out_g = (const float*)d_in[9];
    const float* out_b = (const float*)d_in[10];

    float* out  = (float*)d_out;
    float* attn = out + (size_t)64 * 1024 * 512;

    __nv_bfloat16 *xsp, *hsp, *ctxsp, *attnsp, *esumT, *enc2T, *winsp, *woutsp;
    cudaGetSymbolAddress((void**)&xsp,    g_xsplit);
    cudaGetSymbolAddress((void**)&hsp,    g_hsplit);
    cudaGetSymbolAddress((void**)&ctxsp,  g_ctxsplit);
    cudaGetSymbolAddress((void**)&attnsp, g_attnsplit);
    cudaGetSymbolAddress((void**)&esumT,  g_esumT);
    cudaGetSymbolAddress((void**)&enc2T,  g_enc2T);
    cudaGetSymbolAddress((void**)&winsp,  g_winsplit);
    cudaGetSymbolAddress((void**)&woutsp, g_woutsplit);

    cudaFuncSetAttribute(mma_gemm<0,512>,  cudaFuncAttributeMaxDynamicSharedMemorySize, SMEM_BYTES);
    cudaFuncSetAttribute(mma_gemm<1,512>,  cudaFuncAttributeMaxDynamicSharedMemorySize, SMEM_BYTES);
    cudaFuncSetAttribute(mma_gemm<2,1024>, cudaFuncAttributeMaxDynamicSharedMemorySize, SMEM_BYTES);
    cudaFuncSetAttribute(mma_gemm<3,512>,  cudaFuncAttributeMaxDynamicSharedMemorySize, SMEM_BYTES);

    // ---- operand preparation ----
    wn_split_kernel<<<512, 256>>>(in_v,  in_g,  winsp,  512);
    wn_split_kernel<<<512, 256>>>(out_v, out_g, woutsp, 512);
    asplit_kernel<<<16384, 256>>>(x, xsp);
    // esumT: (enc0+enc1) [b,512,1024] -> [b,1024, 2*512]
    transpose_split_kernel<<<dim3(8, 32, 64), 256>>>(
        enc0, enc1, esumT, 512, 1024, (long long)512 * 1024, (long long)1024 * 1024);
    // enc2T: enc2 [b,1024,512] -> [b,512, 2*1024]
    transpose_split_kernel<<<dim3(16, 16, 64), 256>>>(
        enc2, nullptr, enc2T, 1024, 512, (long long)1024 * 512, (long long)512 * 2048);

    // K1: h = (x@Win^T + b + te)*sqrt(.5) -> hsplit   M=65536 N=512 KLOG=512
    mma_gemm<3,512><<<dim3(4, 512, 1), 256, SMEM_BYTES>>>(
        xsp, winsp, nullptr, hsp, 512, 0LL, 0LL, 0LL, in_b, te, SQRT_HALF_F);

    // K2: scores = h @ esum   per batch M=1024 N=1024 KLOG=512 -> attn (f32)
    mma_gemm<0,512><<<dim3(8, 8, 64), 256, SMEM_BYTES>>>(
        hsp, esumT, attn, nullptr, 1024,
        (long long)1024 * 1024, (long long)1024 * 1024, (long long)1024 * 1024,
        nullptr, nullptr, 1.0f);

    // K3: softmax + split
    softmax_split_kernel<<<65536, 256>>>(attn, attnsp);

    // K4: ctx = (attn @ enc2)*32 -> ctxsplit   per batch M=1024 N=512 KLOG=1024
    mma_gemm<2,1024><<<dim3(4, 8, 64), 256, SMEM_BYTES>>>(
        attnsp, enc2T, nullptr, ctxsp, 512,
        (long long)1024 * 2048, (long long)512 * 2048, (long long)1024 * 1024,
        nullptr, nullptr, 32.0f);

    // K5: out = (ctx@Wout^T + b + x)*sqrt(.5)  M=65536 N=512 KLOG=512 (f32)
    mma_gemm<1,512><<<dim3(4, 512, 1), 256, SMEM_BYTES>>>(
        ctxsp, woutsp, out, nullptr, 512, 0LL, 0LL, 0LL, out_b, x, SQRT_HALF_F);
}